// round 9
// baseline (speedup 1.0000x reference)
#include <cuda_runtime.h>
#include <cuda_fp16.h>
#include <cstdint>

#define BB 4
#define SS 2048
#define DD 1024
#define MTOT (BB*SS)   // 8192

// Static device scratch
__device__ __half g_X [(long)MTOT*DD];
__device__ __half g_Y [(long)MTOT*DD];
__device__ __half g_Z [(long)MTOT*DD];
__device__ __half g_W [3][(long)DD*DD];
__device__ __half g_Q [(long)MTOT*DD];
__device__ __half g_K [(long)MTOT*DD];
__device__ __half g_Vt[(long)BB*DD*SS];    // V transposed: [b][d][s]
__device__ __half g_P [(long)BB*SS*SS];    // exp(scores) fp16 (unnormalized)
__device__ float  g_RS[MTOT];              // per-row sums of exp

// Geometry: CTA 128x128, 8 warps (2x4), warp tile 64x32, BK=64 halves.
#define NTHR     256
#define STAGES   3
#define A_BYTES  16384u
#define STG      32768u            // A 16KB + B 16KB
#define SMEMSZ   (STAGES * STG)    // 96 KB -> 2 CTAs/SM

__device__ __forceinline__ uint32_t smem_u32(const void* p) {
    uint32_t a;
    asm("{ .reg .u64 t; cvta.to.shared.u64 t, %1; cvt.u32.u64 %0, t; }"
        : "=r"(a) : "l"(p));
    return a;
}
__device__ __forceinline__ void cp16(uint32_t s, const void* g) {
    asm volatile("cp.async.cg.shared.global [%0], [%1], 16;" :: "r"(s), "l"(g));
}

#define LDSM4(r, addr) \
    asm volatile("ldmatrix.sync.aligned.m8n8.x4.shared.b16 {%0,%1,%2,%3}, [%4];" \
        : "=r"((r)[0]), "=r"((r)[1]), "=r"((r)[2]), "=r"((r)[3]) : "r"(addr))

#define MMA_F16(c, a, b0, b1) \
    asm volatile("mma.sync.aligned.m16n8k16.row.col.f32.f16.f16.f32 " \
        "{%0,%1,%2,%3}, {%4,%5,%6,%7}, {%8,%9}, {%0,%1,%2,%3};" \
        : "+f"((c)[0]), "+f"((c)[1]), "+f"((c)[2]), "+f"((c)[3]) \
        : "r"((a)[0]), "r"((a)[1]), "r"((a)[2]), "r"((a)[3]), "r"(b0), "r"(b1))

// ---------------------------------------------------------------------------
// fp32 -> fp16 conversion (3 tensors via blockIdx.z); 8 floats per thread.
// ---------------------------------------------------------------------------
__global__ void cvt3_half(const float4* __restrict__ i0, __half* __restrict__ o0,
                          const float4* __restrict__ i1, __half* __restrict__ o1,
                          const float4* __restrict__ i2, __half* __restrict__ o2)
{
    const long i = blockIdx.x * (long)blockDim.x + threadIdx.x;
    const float4* in;
    __half* out;
    if (blockIdx.z == 0)      { in = i0; out = o0; }
    else if (blockIdx.z == 1) { in = i1; out = o1; }
    else                      { in = i2; out = o2; }
    float4 a = in[2 * i], b = in[2 * i + 1];
    __half2 h[4];
    h[0] = __floats2half2_rn(a.x, a.y);
    h[1] = __floats2half2_rn(a.z, a.w);
    h[2] = __floats2half2_rn(b.x, b.y);
    h[3] = __floats2half2_rn(b.z, b.w);
    *(uint4*)(out + 8 * i) = *(uint4*)h;
}

__global__ void zero_rs(float* __restrict__ rs)
{
    rs[blockIdx.x * 1024 + threadIdx.x] = 0.0f;
}

// ---------------------------------------------------------------------------
// Persistent GEMM with CONTINUOUS cross-tile cp.async pipeline.
// MODE 0: QKV projection (tiles z(3) x 64m x 8n = 1536, K=1024)
// MODE 1: scores P = exp(QK^T/32) + row sums (4 x 16m x 16n = 1024, K=1024)
// MODE 2: PV out = (P Vt^T)/rowsum        (4 x 16m x 8n  = 512,  K=2048)
// ---------------------------------------------------------------------------
template<int MODE>
__global__ __launch_bounds__(NTHR, 2)
void gemm_pers(const __half* __restrict__ A0, const __half* __restrict__ A1,
               const __half* __restrict__ A2, const __half* __restrict__ B0,
               const float* __restrict__ x0, const float* __restrict__ x1,
               const float* __restrict__ x2,
               float* __restrict__ of, __half* __restrict__ oh0,
               __half* __restrict__ oh1, __half* __restrict__ oh2,
               float* __restrict__ rs)
{
    constexpr int KT    = (MODE == 2) ? 32 : 16;
    constexpr int LOGKT = (MODE == 2) ? 5 : 4;
    constexpr int NTILE = (MODE == 0) ? 1536 : (MODE == 1) ? 1024 : 512;
    constexpr int LD    = (MODE == 2) ? SS : DD;

    extern __shared__ __align__(1024) char smem[];
    const uint32_t sbase = smem_u32(smem);
    const int tid  = threadIdx.x;
    const int lane = tid & 31;
    const int wid  = tid >> 5;
    const int wm   = wid & 1;
    const int wn   = wid >> 1;
    const int bid  = blockIdx.x;
    const int G    = gridDim.x;

    // per-thread cp.async mapping: 4 chunks A + 4 chunks B
    int offG[4];
    uint32_t sw[4];
#pragma unroll
    for (int i = 0; i < 4; i++) {
        const int idx = i * NTHR + tid;
        const int row = idx >> 3;
        const int c   = idx & 7;
        const uint32_t off = (uint32_t)row * 128u + (uint32_t)c * 16u;
        sw[i]   = off ^ ((off >> 3) & 0x70u);
        offG[i] = row * LD + c * 8;
    }

    // fragment smem addressing (warp tile 64x32)
    const int r16 = lane & 15;
    const uint32_t hi16 = (uint32_t)(lane >> 4) * 16u;
    uint32_t aBase[4], aXor[4], bBase[2], bXor[2];
#pragma unroll
    for (int mt = 0; mt < 4; mt++) {
        const int row = wm * 64 + mt * 16 + r16;
        aBase[mt] = (uint32_t)row * 128u;
        aXor[mt]  = ((uint32_t)(row & 7) << 4);
    }
#pragma unroll
    for (int p = 0; p < 2; p++) {
        const int row = wn * 32 + p * 16 + r16;
        bBase[p] = A_BYTES + (uint32_t)row * 128u;
        bXor[p]  = ((uint32_t)(row & 7) << 4);
    }

    // tile decode -> global A/B element offsets (all < 2^31)
    auto tileAB = [&](int t, int& aOff, int& bOff) {
        if (MODE == 0) {
            const int z   = t >> 9;
            const int rem = t & 511;
            aOff = (rem >> 3) * 128 * DD;          // + selects A0/A1/A2 later
            bOff = z * DD * DD + (rem & 7) * 128 * DD;
        } else if (MODE == 1) {
            const int bz = t >> 8;
            aOff = bz * SS * DD + ((t >> 4) & 15) * 128 * DD;
            bOff = bz * SS * DD + (t & 15) * 128 * DD;
        } else {
            const int bz = t >> 7;
            aOff = bz * SS * SS + ((t >> 3) & 15) * 128 * SS;
            bOff = bz * DD * SS + (t & 7) * 128 * SS;
        }
    };

    auto issue = [&](int l, int st) {
        const int t   = bid + (l >> LOGKT) * G;
        const int kel = (l & (KT - 1)) << 6;
        int aOff, bOff;
        tileAB(t, aOff, bOff);
        const __half* Ap;
        if (MODE == 0) {
            const int z = t >> 9;
            Ap = ((z == 0) ? A0 : (z == 1) ? A1 : A2) + aOff;
        } else {
            Ap = A0 + aOff;
        }
        const __half* Bp = B0 + bOff;
        const uint32_t s0 = sbase + (uint32_t)st * STG;
#pragma unroll
        for (int i = 0; i < 4; i++) cp16(s0 + sw[i], Ap + offG[i] + kel);
#pragma unroll
        for (int i = 0; i < 4; i++) cp16(s0 + A_BYTES + sw[i], Bp + offG[i] + kel);
        asm volatile("cp.async.commit_group;" ::: "memory");
    };

    const int myTiles = (NTILE - 1 - bid) / G + 1;
    const int total   = myTiles * KT;

    float acc[4][4][4];
#pragma unroll
    for (int mt = 0; mt < 4; mt++)
#pragma unroll
        for (int nt = 0; nt < 4; nt++)
#pragma unroll
            for (int i = 0; i < 4; i++) acc[mt][nt][i] = 0.0f;

    issue(0, 0);
    issue(1, 1);

    int st = 0;
    const int g  = lane >> 2;
    const int tg = lane & 3;

    for (int l = 0; l < total; l++) {
        asm volatile("cp.async.wait_group %0;" :: "n"(STAGES - 2));
        __syncthreads();

        int st2 = st + 2; if (st2 >= 3) st2 -= 3;
        if (l + 2 < total) issue(l + 2, st2);
        else asm volatile("cp.async.commit_group;" ::: "memory");

        const uint32_t base = sbase + (uint32_t)st * STG;
#pragma unroll
        for (int kc = 0; kc < 4; kc++) {
            const uint32_t kb = (uint32_t)kc * 32u + hi16;
            uint32_t af[4][4], bf[2][4];
#pragma unroll
            for (int mt = 0; mt < 4; mt++)
                LDSM4(af[mt], base + aBase[mt] + (kb ^ aXor[mt]));
#pragma unroll
            for (int p = 0; p < 2; p++)
                LDSM4(bf[p],  base + bBase[p] + (kb ^ bXor[p]));
#pragma unroll
            for (int mt = 0; mt < 4; mt++)
#pragma unroll
                for (int nt = 0; nt < 4; nt++)
                    MMA_F16(acc[mt][nt], af[mt],
                            bf[nt >> 1][nt & 1],
                            bf[nt >> 1][(nt & 1) + 2]);
        }
        if (++st == 3) st = 0;

        if ((l & (KT - 1)) == KT - 1) {
            // ---- epilogue for tile t
            const int t = bid + (l >> LOGKT) * G;
            if (MODE == 0) {
                const int z   = t >> 9;
                const int rem = t & 511;
                const int bm  = (rem >> 3) * 128;
                const int bn  = (rem & 7) * 128;
                const float* bias = (z == 0) ? x0 : (z == 1) ? x1 : x2;
#pragma unroll
                for (int mt = 0; mt < 4; mt++) {
#pragma unroll
                    for (int nt = 0; nt < 4; nt++) {
                        const int n = bn + wn * 32 + nt * 8 + tg * 2;
                        float2 bv = *(const float2*)(bias + n);
#pragma unroll
                        for (int h = 0; h < 2; h++) {
                            const int m = bm + wm * 64 + mt * 16 + g + h * 8;
                            const float v0 = acc[mt][nt][h * 2 + 0] + bv.x;
                            const float v1 = acc[mt][nt][h * 2 + 1] + bv.y;
                            if (z == 2) {
                                const int b = m >> 11;
                                const int s = m & (SS - 1);
                                const long o = ((long)b * DD + n) * SS + s;
                                oh2[o]      = __float2half_rn(v0);
                                oh2[o + SS] = __float2half_rn(v1);
                            } else {
                                __half* C = (z == 0) ? oh0 : oh1;
                                *(__half2*)(C + (long)m * DD + n) =
                                    __floats2half2_rn(v0, v1);
                            }
                        }
                    }
                }
            } else if (MODE == 1) {
                const int bz = t >> 8;
                const int bm = ((t >> 4) & 15) * 128;
                const int bn = (t & 15) * 128;
                __half* Pb = oh0 + (long)bz * SS * SS;
                float* rsb = rs + bz * SS;
#pragma unroll
                for (int mt = 0; mt < 4; mt++) {
                    float s0 = 0.0f, s1 = 0.0f;
                    const int m0 = bm + wm * 64 + mt * 16 + g;
#pragma unroll
                    for (int nt = 0; nt < 4; nt++) {
                        const int n = bn + wn * 32 + nt * 8 + tg * 2;
                        const float e00 = __expf(acc[mt][nt][0] * 0.03125f);
                        const float e01 = __expf(acc[mt][nt][1] * 0.03125f);
                        const float e10 = __expf(acc[mt][nt][2] * 0.03125f);
                        const float e11 = __expf(acc[mt][nt][3] * 0.03125f);
                        s0 += e00 + e01;
                        s1 += e10 + e11;
                        *(__half2*)(Pb + (long)m0 * SS + n) =
                            __floats2half2_rn(e00, e01);
                        *(__half2*)(Pb + (long)(m0 + 8) * SS + n) =
                            __floats2half2_rn(e10, e11);
                    }
                    s0 += __shfl_xor_sync(~0u, s0, 1);
                    s0 += __shfl_xor_sync(~0u, s0, 2);
                    s1 += __shfl_xor_sync(~0u, s1, 1);
                    s1 += __shfl_xor_sync(~0u, s1, 2);
                    if (tg == 0) {
                        atomicAdd(&rsb[m0],     s0);
                        atomicAdd(&rsb[m0 + 8], s1);
                    }
                }
            } else {
                const int bz = t >> 7;
                const int bm = ((t >> 3) & 15) * 128;
                const int bn = (t & 7) * 128;
                const float* rsb = rs + bz * SS;
                float* C = of + (long)bz * SS * DD;
#pragma unroll
                for (int mt = 0; mt < 4; mt++) {
                    const int m0 = bm + wm * 64 + mt * 16 + g;
                    const float i0 = 1.0f / __ldg(&rsb[m0]);
                    const float i1 = 1.0f / __ldg(&rsb[m0 + 8]);
#pragma unroll
                    for (int nt = 0; nt < 4; nt++) {
                        const int n = bn + wn * 32 + nt * 8 + tg * 2;
                        float2 v0, v1;
                        v0.x = acc[mt][nt][0] * i0;
                        v0.y = acc[mt][nt][1] * i0;
                        v1.x = acc[mt][nt][2] * i1;
                        v1.y = acc[mt][nt][3] * i1;
                        *(float2*)(C + (long)m0 * DD + n)       = v0;
                        *(float2*)(C + (long)(m0 + 8) * DD + n) = v1;
                    }
                }
            }
            // reset accumulators for next tile
#pragma unroll
            for (int mt = 0; mt < 4; mt++)
#pragma unroll
                for (int nt = 0; nt < 4; nt++)
#pragma unroll
                    for (int i = 0; i < 4; i++) acc[mt][nt][i] = 0.0f;
        }
    }
}

extern "C" void kernel_launch(void* const* d_in, const int* in_sizes, int n_in,
                              void* d_out, int out_size)
{
    const float* x  = (const float*)d_in[0];
    const float* y  = (const float*)d_in[1];
    const float* z  = (const float*)d_in[2];
    const float* Wq = (const float*)d_in[3];
    const float* bq = (const float*)d_in[4];
    const float* Wk = (const float*)d_in[5];
    const float* bk = (const float*)d_in[6];
    const float* Wv = (const float*)d_in[7];
    const float* bv = (const float*)d_in[8];
    float* out = (float*)d_out;

    void *pX, *pY, *pZ, *pW, *pQ, *pK, *pV, *pP, *pRS;
    cudaGetSymbolAddress(&pX,  g_X);
    cudaGetSymbolAddress(&pY,  g_Y);
    cudaGetSymbolAddress(&pZ,  g_Z);
    cudaGetSymbolAddress(&pW,  g_W);
    cudaGetSymbolAddress(&pQ,  g_Q);
    cudaGetSymbolAddress(&pK,  g_K);
    cudaGetSymbolAddress(&pV,  g_Vt);
    cudaGetSymbolAddress(&pP,  g_P);
    cudaGetSymbolAddress(&pRS, g_RS);
    __half* X  = (__half*)pX;
    __half* Y  = (__half*)pY;
    __half* Z  = (__half*)pZ;
    __half* W  = (__half*)pW;
    __half* Q  = (__half*)pQ;
    __half* Kb = (__half*)pK;
    __half* Vt = (__half*)pV;
    __half* P  = (__half*)pP;
    float*  RS = (float*)pRS;

    int nsm = 148;
    cudaDeviceGetAttribute(&nsm, cudaDevAttrMultiProcessorCount, 0);
    const int grid = 2 * nsm;

    cudaFuncSetAttribute(gemm_pers<0>, cudaFuncAttributeMaxDynamicSharedMemorySize, SMEMSZ);
    cudaFuncSetAttribute(gemm_pers<1>, cudaFuncAttributeMaxDynamicSharedMemorySize, SMEMSZ);
    cudaFuncSetAttribute(gemm_pers<2>, cudaFuncAttributeMaxDynamicSharedMemorySize, SMEMSZ);

    // 0) zero row sums + convert inputs to fp16
    zero_rs<<<MTOT / 1024, 1024>>>(RS);
    {
        dim3 gb((MTOT * (long)DD) / (8 * 256), 1, 3);
        cvt3_half<<<gb, 256>>>((const float4*)x, X,
                               (const float4*)y, Y,
                               (const float4*)z, Z);
        dim3 gw(((long)DD * DD) / (8 * 256), 1, 3);
        cvt3_half<<<gw, 256>>>((const float4*)Wq, W,
                               (const float4*)Wk, W + (long)DD * DD,
                               (const float4*)Wv, W + 2 * (long)DD * DD);
    }
    // 1) QKV projections (V transposed)
    gemm_pers<0><<<grid, NTHR, SMEMSZ>>>(X, Y, Z, W, bq, bk, bv,
                                         nullptr, Q, Kb, Vt, nullptr);
    // 2) P = exp(Q K^T / 32) + row sums
    gemm_pers<1><<<grid, NTHR, SMEMSZ>>>(Q, nullptr, nullptr, Kb,
                                         nullptr, nullptr, nullptr,
                                         nullptr, P, nullptr, nullptr, RS);
    // 3) out = (P @ Vt^T) / rowsum
    gemm_pers<2><<<grid, NTHR, SMEMSZ>>>(P, nullptr, nullptr, Vt,
                                         nullptr, nullptr, nullptr,
                                         out, nullptr, nullptr, nullptr, RS);
}

// round 10
// speedup vs baseline: 1.0596x; 1.0596x over previous
#include <cuda_runtime.h>
#include <cuda_fp16.h>
#include <cstdint>

#define BB 4
#define SS 2048
#define DD 1024
#define MTOT (BB*SS)   // 8192

// Static device scratch
__device__ __half g_X [(long)MTOT*DD];
__device__ __half g_Y [(long)MTOT*DD];
__device__ __half g_Z [(long)MTOT*DD];
__device__ __half g_W [3][(long)DD*DD];
__device__ __half g_Q [(long)MTOT*DD];
__device__ __half g_K [(long)MTOT*DD];
__device__ __half g_Vt[(long)BB*DD*SS];    // V transposed: [b][d][s]
__device__ __half g_P [(long)BB*SS*SS];    // exp(scores) fp16 (unnormalized)
__device__ float  g_RS[MTOT];              // per-row sums of exp

// ---------------------------------------------------------------------------
// helpers
// ---------------------------------------------------------------------------
__device__ __forceinline__ uint32_t smem_u32(const void* p) {
    uint32_t a;
    asm("{ .reg .u64 t; cvta.to.shared.u64 t, %1; cvt.u32.u64 %0, t; }"
        : "=r"(a) : "l"(p));
    return a;
}
__device__ __forceinline__ void cp16(uint32_t s, const void* g) {
    asm volatile("cp.async.cg.shared.global [%0], [%1], 16;" :: "r"(s), "l"(g));
}

#define LDSM4(r, addr) \
    asm volatile("ldmatrix.sync.aligned.m8n8.x4.shared.b16 {%0,%1,%2,%3}, [%4];" \
        : "=r"((r)[0]), "=r"((r)[1]), "=r"((r)[2]), "=r"((r)[3]) : "r"(addr))

#define MMA_F16(c, a, b0, b1) \
    asm volatile("mma.sync.aligned.m16n8k16.row.col.f32.f16.f16.f32 " \
        "{%0,%1,%2,%3}, {%4,%5,%6,%7}, {%8,%9}, {%0,%1,%2,%3};" \
        : "+f"((c)[0]), "+f"((c)[1]), "+f"((c)[2]), "+f"((c)[3]) \
        : "r"((a)[0]), "r"((a)[1]), "r"((a)[2]), "r"((a)[3]), "r"(b0), "r"(b1))

// ---------------------------------------------------------------------------
// fp32 -> fp16 conversion (3 tensors via blockIdx.z); 8 floats per thread.
// z==0 blocks additionally zero the RS array (folded zero_rs).
// ---------------------------------------------------------------------------
__global__ void cvt3_half(const float4* __restrict__ i0, __half* __restrict__ o0,
                          const float4* __restrict__ i1, __half* __restrict__ o1,
                          const float4* __restrict__ i2, __half* __restrict__ o2,
                          float* __restrict__ rs)
{
    const long i = blockIdx.x * (long)blockDim.x + threadIdx.x;
    if (rs != nullptr && blockIdx.z == 0 && i < MTOT) rs[i] = 0.0f;
    const float4* in;
    __half* out;
    if (blockIdx.z == 0)      { in = i0; out = o0; }
    else if (blockIdx.z == 1) { in = i1; out = o1; }
    else                      { in = i2; out = o2; }
    float4 a = in[2 * i], b = in[2 * i + 1];
    __half2 h[4];
    h[0] = __floats2half2_rn(a.x, a.y);
    h[1] = __floats2half2_rn(a.z, a.w);
    h[2] = __floats2half2_rn(b.x, b.y);
    h[3] = __floats2half2_rn(b.z, b.w);
    *(uint4*)(out + 8 * i) = *(uint4*)h;
}

// ---------------------------------------------------------------------------
// Shared fp16 NT GEMM mainloop with ROLLING FRAGMENT PREFETCH.
// acc = A[128,K] @ B[128,K]^T; K contiguous; SW128 128B rows; 3-stage
// cp.async; 8 warps (2x4), warp tile 64x32; fp32 accumulate.
// Inner loop ping-pongs af (by mt parity) and bf (by kc parity) so every
// ldmatrix is issued one MMA-block ahead of its consumer.
// ---------------------------------------------------------------------------
__device__ __forceinline__ void mainloop_h(
    const __half* __restrict__ A, const __half* __restrict__ B,
    int K, int lda, int ldb, uint32_t sbase,
    int tid, int lane, int wm, int wn, float acc[4][4][4])
{
    constexpr int STAGES = 3;
    constexpr uint32_t STG_BYTES = 32768;

    const __half* ga[4];
    const __half* gb[4];
    uint32_t sw[4];
#pragma unroll
    for (int i = 0; i < 4; i++) {
        const int idx = i * 256 + tid;
        const int row = idx >> 3;
        const int c   = idx & 7;
        const uint32_t off = (uint32_t)row * 128u + (uint32_t)c * 16u;
        sw[i] = off ^ ((off >> 3) & 0x70u);
        ga[i] = A + (long)row * lda + c * 8;
        gb[i] = B + (long)row * ldb + c * 8;
    }

    auto issue = [&](int kt, int st) {
        const uint32_t s0 = sbase + (uint32_t)st * STG_BYTES;
#pragma unroll
        for (int i = 0; i < 4; i++) cp16(s0 + sw[i], ga[i] + (long)kt * 64);
#pragma unroll
        for (int i = 0; i < 4; i++) cp16(s0 + 16384u + sw[i], gb[i] + (long)kt * 64);
        asm volatile("cp.async.commit_group;" ::: "memory");
    };

    const int r16 = lane & 15;
    const uint32_t hi16 = (uint32_t)(lane >> 4) * 16u;
    uint32_t aBase[4], aXor[4], bBase[2], bXor[2];
#pragma unroll
    for (int mt = 0; mt < 4; mt++) {
        const int row = wm * 64 + mt * 16 + r16;
        aBase[mt] = (uint32_t)row * 128u;
        aXor[mt]  = ((uint32_t)(row & 7) << 4);
    }
#pragma unroll
    for (int p = 0; p < 2; p++) {
        const int row = wn * 32 + p * 16 + r16;
        bBase[p] = 16384u + (uint32_t)row * 128u;
        bXor[p]  = ((uint32_t)(row & 7) << 4);
    }

    const int KT = K >> 6;
#pragma unroll
    for (int s = 0; s < STAGES - 1; s++) issue(s, s);

    for (int kt = 0; kt < KT; kt++) {
        asm volatile("cp.async.wait_group %0;" :: "n"(STAGES - 2));
        __syncthreads();

        const int pf = kt + STAGES - 1;
        if (pf < KT) issue(pf, pf % STAGES);
        else asm volatile("cp.async.commit_group;" ::: "memory");

        const uint32_t base = sbase + (uint32_t)(kt % STAGES) * STG_BYTES;

        uint32_t af[2][4];      // ping-pong by mt parity
        uint32_t bf[2][2][4];   // ping-pong by kc parity

        // preload kc=0 fragments: both B blocks + first A block
        LDSM4(bf[0][0], base + bBase[0] + (hi16 ^ bXor[0]));
        LDSM4(bf[0][1], base + bBase[1] + (hi16 ^ bXor[1]));
        LDSM4(af[0],    base + aBase[0] + (hi16 ^ aXor[0]));

#pragma unroll
        for (int kc = 0; kc < 4; kc++) {
            const uint32_t kb  = (uint32_t)kc * 32u + hi16;
            const uint32_t kbn = kb + 32u;            // next kc
#pragma unroll
            for (int mt = 0; mt < 4; mt++) {
                // prefetch the NEXT fragment(s) before this block's MMAs
                if (mt < 3) {
                    LDSM4(af[(mt + 1) & 1],
                          base + aBase[mt + 1] + (kb ^ aXor[mt + 1]));
                } else if (kc < 3) {
                    LDSM4(bf[(kc + 1) & 1][0], base + bBase[0] + (kbn ^ bXor[0]));
                    LDSM4(bf[(kc + 1) & 1][1], base + bBase[1] + (kbn ^ bXor[1]));
                    LDSM4(af[0],               base + aBase[0] + (kbn ^ aXor[0]));
                }
#pragma unroll
                for (int nt = 0; nt < 4; nt++)
                    MMA_F16(acc[mt][nt], af[mt & 1],
                            bf[kc & 1][nt >> 1][nt & 1],
                            bf[kc & 1][nt >> 1][(nt & 1) + 2]);
            }
        }
    }
}

// ---------------------------------------------------------------------------
// Merged QKV projection: z = blockIdx.z selects (input, W, bias, output).
// z==2 (V) stores transposed per batch: Vt[(b*DD + n)*SS + s].
// ---------------------------------------------------------------------------
__global__ __launch_bounds__(256, 2)
void gemm_proj(const __half* __restrict__ Ax, const __half* __restrict__ Ay,
               const __half* __restrict__ Az, const __half* __restrict__ W,
               const float* __restrict__ b0, const float* __restrict__ b1,
               const float* __restrict__ b2,
               __half* __restrict__ Qo, __half* __restrict__ Ko,
               __half* __restrict__ Vt)
{
    extern __shared__ __align__(1024) char smem[];
    const uint32_t sbase = smem_u32(smem);
    const int tid  = threadIdx.x;
    const int lane = tid & 31;
    const int wid  = tid >> 5;
    const int wm   = wid & 1;
    const int wn   = wid >> 1;
    const int bm   = blockIdx.y * 128;
    const int bn   = blockIdx.x * 128;
    const int z    = blockIdx.z;

    const __half* A = (z == 0) ? Ax : (z == 1) ? Ay : Az;
    const __half* B = W + (long)z * DD * DD;
    const float* bias = (z == 0) ? b0 : (z == 1) ? b1 : b2;

    float acc[4][4][4];
#pragma unroll
    for (int mt = 0; mt < 4; mt++)
#pragma unroll
        for (int nt = 0; nt < 4; nt++)
#pragma unroll
            for (int i = 0; i < 4; i++) acc[mt][nt][i] = 0.0f;

    mainloop_h(A + (long)bm * DD, B + (long)bn * DD, DD, DD, DD,
               sbase, tid, lane, wm, wn, acc);

    const int g  = lane >> 2;
    const int tg = lane & 3;
#pragma unroll
    for (int mt = 0; mt < 4; mt++) {
#pragma unroll
        for (int nt = 0; nt < 4; nt++) {
            const int n = bn + wn * 32 + nt * 8 + tg * 2;
            float2 bv = *(const float2*)(bias + n);
#pragma unroll
            for (int h = 0; h < 2; h++) {
                const int m = bm + wm * 64 + mt * 16 + g + h * 8;
                const float v0 = acc[mt][nt][h * 2 + 0] + bv.x;
                const float v1 = acc[mt][nt][h * 2 + 1] + bv.y;
                if (z == 2) {
                    const int b = m >> 11;
                    const int s = m & (SS - 1);
                    const long o = ((long)b * DD + n) * SS + s;
                    Vt[o]      = __float2half_rn(v0);
                    Vt[o + SS] = __float2half_rn(v1);
                } else {
                    __half* C = (z == 0) ? Qo : Ko;
                    *(__half2*)(C + (long)m * DD + n) = __floats2half2_rn(v0, v1);
                }
            }
        }
    }
}

// ---------------------------------------------------------------------------
// Scores: P = exp(Q @ K^T / 32) (fp16, unnormalized) + atomic row sums.
// ---------------------------------------------------------------------------
__global__ __launch_bounds__(256, 2)
void gemm_scores(const __half* __restrict__ Q, const __half* __restrict__ Kb,
                 __half* __restrict__ P, float* __restrict__ RS)
{
    extern __shared__ __align__(1024) char smem[];
    const uint32_t sbase = smem_u32(smem);
    const int tid  = threadIdx.x;
    const int lane = tid & 31;
    const int wid  = tid >> 5;
    const int wm   = wid & 1;
    const int wn   = wid >> 1;
    const int bm   = blockIdx.y * 128;
    const int bn   = blockIdx.x * 128;
    const long bz  = blockIdx.z;

    const __half* A = Q  + bz * SS * DD + (long)bm * DD;
    const __half* B = Kb + bz * SS * DD + (long)bn * DD;
    __half* Pb = P + bz * (long)SS * SS;
    float* rs = RS + bz * SS;

    float acc[4][4][4];
#pragma unroll
    for (int mt = 0; mt < 4; mt++)
#pragma unroll
        for (int nt = 0; nt < 4; nt++)
#pragma unroll
            for (int i = 0; i < 4; i++) acc[mt][nt][i] = 0.0f;

    mainloop_h(A, B, DD, DD, DD, sbase, tid, lane, wm, wn, acc);

    const int g  = lane >> 2;
    const int tg = lane & 3;
#pragma unroll
    for (int mt = 0; mt < 4; mt++) {
        float s0 = 0.0f, s1 = 0.0f;
        const int m0 = bm + wm * 64 + mt * 16 + g;
#pragma unroll
        for (int nt = 0; nt < 4; nt++) {
            const int n = bn + wn * 32 + nt * 8 + tg * 2;
            const float e00 = __expf(acc[mt][nt][0] * 0.03125f);
            const float e01 = __expf(acc[mt][nt][1] * 0.03125f);
            const float e10 = __expf(acc[mt][nt][2] * 0.03125f);
            const float e11 = __expf(acc[mt][nt][3] * 0.03125f);
            s0 += e00 + e01;
            s1 += e10 + e11;
            *(__half2*)(Pb + (long)m0 * SS + n)       = __floats2half2_rn(e00, e01);
            *(__half2*)(Pb + (long)(m0 + 8) * SS + n) = __floats2half2_rn(e10, e11);
        }
        s0 += __shfl_xor_sync(~0u, s0, 1);
        s0 += __shfl_xor_sync(~0u, s0, 2);
        s1 += __shfl_xor_sync(~0u, s1, 1);
        s1 += __shfl_xor_sync(~0u, s1, 2);
        if (tg == 0) {
            atomicAdd(&rs[m0],     s0);
            atomicAdd(&rs[m0 + 8], s1);
        }
    }
}

// ---------------------------------------------------------------------------
// PV: out = (P @ Vt^T) / rowsum  (fp32 out)
// ---------------------------------------------------------------------------
__global__ __launch_bounds__(256, 2)
void gemm_pv(const __half* __restrict__ P, const __half* __restrict__ Vt,
             const float* __restrict__ RS, float* __restrict__ O)
{
    extern __shared__ __align__(1024) char smem[];
    const uint32_t sbase = smem_u32(smem);
    const int tid  = threadIdx.x;
    const int lane = tid & 31;
    const int wid  = tid >> 5;
    const int wm   = wid & 1;
    const int wn   = wid >> 1;
    const int bm   = blockIdx.y * 128;
    const int bn   = blockIdx.x * 128;
    const long bz  = blockIdx.z;

    const __half* A = P  + bz * (long)SS * SS + (long)bm * SS;
    const __half* B = Vt + bz * (long)DD * SS + (long)bn * SS;
    const float* rs = RS + bz * SS;
    float* C = O + bz * (long)SS * DD;

    float acc[4][4][4];
#pragma unroll
    for (int mt = 0; mt < 4; mt++)
#pragma unroll
        for (int nt = 0; nt < 4; nt++)
#pragma unroll
            for (int i = 0; i < 4; i++) acc[mt][nt][i] = 0.0f;

    mainloop_h(A, B, SS, SS, SS, sbase, tid, lane, wm, wn, acc);

    const int g  = lane >> 2;
    const int tg = lane & 3;
#pragma unroll
    for (int mt = 0; mt < 4; mt++) {
        const int m0 = bm + wm * 64 + mt * 16 + g;
        const float i0 = 1.0f / __ldg(&rs[m0]);
        const float i1 = 1.0f / __ldg(&rs[m0 + 8]);
#pragma unroll
        for (int nt = 0; nt < 4; nt++) {
            const int n = bn + wn * 32 + nt * 8 + tg * 2;
            float2 v0, v1;
            v0.x = acc[mt][nt][0] * i0;
            v0.y = acc[mt][nt][1] * i0;
            v1.x = acc[mt][nt][2] * i1;
            v1.y = acc[mt][nt][3] * i1;
            *(float2*)(C + (long)m0 * DD + n)       = v0;
            *(float2*)(C + (long)(m0 + 8) * DD + n) = v1;
        }
    }
}

extern "C" void kernel_launch(void* const* d_in, const int* in_sizes, int n_in,
                              void* d_out, int out_size)
{
    const float* x  = (const float*)d_in[0];
    const float* y  = (const float*)d_in[1];
    const float* z  = (const float*)d_in[2];
    const float* Wq = (const float*)d_in[3];
    const float* bq = (const float*)d_in[4];
    const float* Wk = (const float*)d_in[5];
    const float* bk = (const float*)d_in[6];
    const float* Wv = (const float*)d_in[7];
    const float* bv = (const float*)d_in[8];
    float* out = (float*)d_out;

    void *pX, *pY, *pZ, *pW, *pQ, *pK, *pV, *pP, *pRS;
    cudaGetSymbolAddress(&pX,  g_X);
    cudaGetSymbolAddress(&pY,  g_Y);
    cudaGetSymbolAddress(&pZ,  g_Z);
    cudaGetSymbolAddress(&pW,  g_W);
    cudaGetSymbolAddress(&pQ,  g_Q);
    cudaGetSymbolAddress(&pK,  g_K);
    cudaGetSymbolAddress(&pV,  g_Vt);
    cudaGetSymbolAddress(&pP,  g_P);
    cudaGetSymbolAddress(&pRS, g_RS);
    __half* X  = (__half*)pX;
    __half* Y  = (__half*)pY;
    __half* Z  = (__half*)pZ;
    __half* W  = (__half*)pW;
    __half* Q  = (__half*)pQ;
    __half* Kb = (__half*)pK;
    __half* Vt = (__half*)pV;
    __half* P  = (__half*)pP;
    float*  RS = (float*)pRS;

    const int SMEMSZ = 3 * 32768;   // 96 KB
    cudaFuncSetAttribute(gemm_proj,   cudaFuncAttributeMaxDynamicSharedMemorySize, SMEMSZ);
    cudaFuncSetAttribute(gemm_scores, cudaFuncAttributeMaxDynamicSharedMemorySize, SMEMSZ);
    cudaFuncSetAttribute(gemm_pv,     cudaFuncAttributeMaxDynamicSharedMemorySize, SMEMSZ);

    // 0) convert inputs to fp16 (z==0 blocks also zero RS)
    {
        dim3 gb((MTOT * (long)DD) / (8 * 256), 1, 3);
        cvt3_half<<<gb, 256>>>((const float4*)x, X,
                               (const float4*)y, Y,
                               (const float4*)z, Z, RS);
        dim3 gw(((long)DD * DD) / (8 * 256), 1, 3);
        cvt3_half<<<gw, 256>>>((const float4*)Wq, W,
                               (const float4*)Wk, W + (long)DD * DD,
                               (const float4*)Wv, W + 2 * (long)DD * DD, nullptr);
    }
    // 1) merged QKV projections (V transposed)
    {
        dim3 g1(DD / 128, MTOT / 128, 3);
        gemm_proj<<<g1, 256, SMEMSZ>>>(X, Y, Z, W, bq, bk, bv, Q, Kb, Vt);
    }
    // 2) P = exp(Q K^T / 32), row sums via atomics
    {
        dim3 g2(SS / 128, SS / 128, BB);
        gemm_scores<<<g2, 256, SMEMSZ>>>(Q, Kb, P, RS);
    }
    // 3) out = (P @ Vt^T) / rowsum
    {
        dim3 g3(DD / 128, SS / 128, BB);
        gemm_pv<<<g3, 256, SMEMSZ>>>(P, Vt, RS, out);
    }
}